// round 15
// baseline (speedup 1.0000x reference)
#include <cuda_runtime.h>
#include <cstdint>

#define BATCH   32
#define CIN     64
#define COUT    64
#define HH      56
#define WW      56
#define LL      3136
#define FEAT    576
#define NCHUNK  18            // 576 / 32 f
#define KHALF   9             // chunks per k-half
#define NTHREADS 256          // 8 warps = 4 channel-groups x 2 k-halves
#define NWARP   8
#define WDEPTH  3             // register ring depth (chunks)

// ---- smem: patch tile only ----
#define PROW_BYTES  2320      // 580 floats (odd x16 -> ldsm conflict-free)
#define NB          16
#define SMEM_TOTAL  (NB * PROW_BYTES)       // 37120

__device__ float g_xt[(size_t)BATCH * LL * CIN];
__device__ float g_out_s[(size_t)LL * BATCH * COUT];    // [l][b][c]

// ---------------- helpers ----------------
__device__ __forceinline__ uint32_t cvt_tf32(float v) {
    uint32_t t;
    asm("cvt.rna.tf32.f32 %0, %1;" : "=r"(t) : "f"(v));
    return t;
}

__device__ __forceinline__ void sts32(uint32_t a, uint32_t v) {
    asm volatile("st.shared.b32 [%0], %1;" :: "r"(a), "r"(v) : "memory");
}

__device__ __forceinline__ void ldsm_x4(uint32_t addr, uint32_t& r0, uint32_t& r1,
                                        uint32_t& r2, uint32_t& r3) {
    asm volatile("ldmatrix.sync.aligned.m8n8.x4.shared.b16 {%0,%1,%2,%3}, [%4];"
                 : "=r"(r0), "=r"(r1), "=r"(r2), "=r"(r3) : "r"(addr));
}

__device__ __forceinline__ void mma_tf32(float* d, const uint32_t* a, const uint32_t* b) {
    asm volatile("mma.sync.aligned.m16n8k8.row.col.f32.tf32.tf32.f32 "
                 "{%0,%1,%2,%3}, {%4,%5,%6,%7}, {%8,%9}, {%0,%1,%2,%3};"
                 : "+f"(d[0]), "+f"(d[1]), "+f"(d[2]), "+f"(d[3])
                 : "r"(a[0]), "r"(a[1]), "r"(a[2]), "r"(a[3]),
                   "r"(b[0]), "r"(b[1]));
}

// ---------------- kernel 1: x NCHW -> NHWC transpose ----------------
__global__ void __launch_bounds__(256) transpose_x(const float* __restrict__ x) {
    __shared__ float tile[32][33];
    const int b  = blockIdx.z;
    const int c0 = blockIdx.y * 32;
    const int s0 = blockIdx.x * 32;
    const int tx = threadIdx.x & 31;
    const int ty = threadIdx.x >> 5;
    #pragma unroll
    for (int i = 0; i < 4; i++)
        tile[ty + 8 * i][tx] = x[((size_t)b * CIN + c0 + ty + 8 * i) * LL + s0 + tx];
    __syncthreads();
    #pragma unroll
    for (int i = 0; i < 4; i++)
        g_xt[((size_t)b * LL + s0 + ty + 8 * i) * CIN + c0 + tx] = tile[tx][ty + 8 * i];
}

// ---------------- kernel 3: scratch [l][b*64+c] -> out [b*64+c][l] ----------------
__global__ void __launch_bounds__(256) transpose_out(float* __restrict__ out) {
    __shared__ float tile[32][33];
    const int l0 = blockIdx.x * 32;
    const int m0 = blockIdx.y * 32;        // m = b*64 + c
    const int tx = threadIdx.x & 31;
    const int ty = threadIdx.x >> 5;
    #pragma unroll
    for (int i = 0; i < 4; i++)
        tile[ty + 8 * i][tx] = g_out_s[(size_t)(l0 + ty + 8 * i) * (BATCH * COUT) + m0 + tx];
    __syncthreads();
    #pragma unroll
    for (int i = 0; i < 4; i++)
        out[(size_t)(m0 + ty + 8 * i) * LL + l0 + tx] = tile[tx][ty + 8 * i];
}

// ---------------- kernel 2: GEMM, weights gmem->reg direct ----------------
__global__ void __launch_bounds__(NTHREADS, 2)
lc2d_mma(const float* __restrict__ w,
         const float* __restrict__ bias)
{
    extern __shared__ __align__(128) char smem[];
    const uint32_t sb = (uint32_t)__cvta_generic_to_shared(smem);

    const int tid  = threadIdx.x;
    const int lane = tid & 31;
    const int warp = tid >> 5;
    const int kh   = warp & 1;        // k half: chunks [9*kh, 9*kh+9)
    const int cg   = warp >> 1;       // channel group: channels [16*cg, 16*cg+16)
    const int l    = blockIdx.x >> 1;
    const int half = blockIdx.x & 1;  // batches [16*half, 16*half+16)
    const int oh   = l / WW;
    const int ow   = l - oh * WW;

    // ---- B (weight) direct-LDG base pointers ----
    // thread t supplies B[n = nt*8 + (t>>2)][k = ks*8 + (t&3) (+4)]
    // gmem: w[l*64*576 + c*576 + f], c = cg*16 + nt*8 + (t>>2), f = kh*288 + k*32 + ks*8 + (t&3)
    const float* wp0 = w + (size_t)l * (COUT * FEAT)
                     + (size_t)(cg * 16 + (lane >> 2)) * FEAT
                     + kh * (KHALF * 32) + (lane & 3);
    const float* wp1 = wp0 + 8 * FEAT;    // nt = 1

    // register ring: wr[slot][nt*8 + ks*2 + j]
    float wr[WDEPTH][16];

    #define LOAD_CHUNK(slot, k)                                            \
        do {                                                               \
            _Pragma("unroll")                                              \
            for (int ks = 0; ks < 4; ks++) {                               \
                wr[slot][ks * 2 + 0]     = wp0[(k) * 32 + ks * 8];         \
                wr[slot][ks * 2 + 1]     = wp0[(k) * 32 + ks * 8 + 4];     \
                wr[slot][8 + ks * 2 + 0] = wp1[(k) * 32 + ks * 8];         \
                wr[slot][8 + ks * 2 + 1] = wp1[(k) * 32 + ks * 8 + 4];     \
            }                                                              \
        } while (0)

    // ---- prologue: prefetch chunks 0..2 into the register ring ----
    LOAD_CHUNK(0, 0);
    LOAD_CHUNK(1, 1);
    LOAD_CHUNK(2, 2);

    // ---- stage patches (16 batches): front-loaded LDGs for MLP ----
    {
        const int pos = tid & 15;                 // cin group: cin = pos*4 + q
        float4   v[9];
        uint32_t adr[9];
        #pragma unroll
        for (int i = 0; i < 9; i++) {
            int s  = (tid >> 4) + i * 16;         // 0..143
            int b  = s / 9;
            int rr = s - b * 9;                   // ki*3 + kj
            int ki = rr / 3, kj = rr - ki * 3;
            int h  = oh + ki - 1;
            int wq = ow + kj - 1;
            bool ok = ((unsigned)h < HH) & ((unsigned)wq < WW);
            v[i] = make_float4(0.f, 0.f, 0.f, 0.f);
            if (ok)
                v[i] = *(const float4*)(g_xt + ((size_t)(half * NB + b) * LL + h * WW + wq) * CIN
                                        + pos * 4);
            adr[i] = sb + (uint32_t)b * PROW_BYTES + (uint32_t)(36 * pos + rr) * 4;
        }
        #pragma unroll
        for (int i = 0; i < 9; i++) {
            sts32(adr[i],       cvt_tf32(v[i].x));
            sts32(adr[i] + 36,  cvt_tf32(v[i].y));
            sts32(adr[i] + 72,  cvt_tf32(v[i].z));
            sts32(adr[i] + 108, cvt_tf32(v[i].w));
        }
    }

    // ---- A fragment addressing (patches) ----
    const uint32_t a_base = sb + (uint32_t)(lane & 15) * PROW_BYTES
                          + ((lane & 16) ? 16u : 0u);

    float acc[2][4];
    #pragma unroll
    for (int nt = 0; nt < 2; nt++)
        #pragma unroll
        for (int q = 0; q < 4; q++) acc[nt][q] = 0.0f;

    __syncthreads();   // patch tile ready

    // ---- main loop: 9 chunks, fully unrolled, weights from register ring ----
    #pragma unroll
    for (int k = 0; k < KHALF; k++) {
        const int kg   = kh * KHALF + k;    // global chunk (A column block)
        const int slot = k % WDEPTH;

        // A-frags for chunk kg
        uint32_t a[4][4];
        #pragma unroll
        for (int ks = 0; ks < 4; ks++)
            ldsm_x4(a_base + (uint32_t)(kg * 128 + ks * 32),
                    a[ks][0], a[ks][1], a[ks][2], a[ks][3]);

        // consume weights from ring slot, cvt to tf32, mma
        #pragma unroll
        for (int ks = 0; ks < 4; ks++) {
            uint32_t bf[4];
            bf[0] = cvt_tf32(wr[slot][ks * 2 + 0]);
            bf[1] = cvt_tf32(wr[slot][ks * 2 + 1]);
            bf[2] = cvt_tf32(wr[slot][8 + ks * 2 + 0]);
            bf[3] = cvt_tf32(wr[slot][8 + ks * 2 + 1]);
            mma_tf32(acc[0], a[ks], bf);        // channels cg*16 + 0..7
            mma_tf32(acc[1], a[ks], bf + 2);    // channels cg*16 + 8..15
        }

        // refill this slot with chunk k+WDEPTH
        if (k + WDEPTH < KHALF)
            LOAD_CHUNK(slot, k + WDEPTH);
    }
    #undef LOAD_CHUNK

    // ---- cross-warp k-reduction (reuse patch smem) + coalesced epilogue ----
    // D m16n8 layout: d0=(g,2t) d1=(g,2t+1) d2=(g+8,2t) d3=(g+8,2t+1)
    const int g  = lane >> 2;
    const int t2 = (lane & 3) * 2;

    __syncthreads();   // all patch reads done; safe to reuse as reduction area
    float* red = (float*)smem;        // [4 cg][16 b][16 c] = 4 KB

    if (kh == 1) {
        float* rb = red + cg * 256;
        #pragma unroll
        for (int nt = 0; nt < 2; nt++) {
            const int c = nt * 8 + t2;
            rb[(g    ) * 16 + c    ] = acc[nt][0];
            rb[(g    ) * 16 + c + 1] = acc[nt][1];
            rb[(g + 8) * 16 + c    ] = acc[nt][2];
            rb[(g + 8) * 16 + c + 1] = acc[nt][3];
        }
    }
    __syncthreads();

    if (kh == 0) {
        const float* rb = red + cg * 256;
        const float* bl = bias + (size_t)l * COUT;
        float* os = g_out_s + (size_t)l * (BATCH * COUT) + (half * NB) * COUT;
        #pragma unroll
        for (int nt = 0; nt < 2; nt++) {
            const int cl = nt * 8 + t2;
            const int c  = cg * 16 + cl;
            const float bv0 = bl[c];
            const float bv1 = bl[c + 1];
            float2 v0, v1;
            v0.x = acc[nt][0] + rb[(g    ) * 16 + cl    ] + bv0;
            v0.y = acc[nt][1] + rb[(g    ) * 16 + cl + 1] + bv1;
            v1.x = acc[nt][2] + rb[(g + 8) * 16 + cl    ] + bv0;
            v1.y = acc[nt][3] + rb[(g + 8) * 16 + cl + 1] + bv1;
            *(float2*)(os + (size_t)(g    ) * COUT + c) = v0;
            *(float2*)(os + (size_t)(g + 8) * COUT + c) = v1;
        }
    }
}

extern "C" void kernel_launch(void* const* d_in, const int* in_sizes, int n_in,
                              void* d_out, int out_size)
{
    const float* x    = (const float*)d_in[0];   // [32,64,56,56]
    const float* w    = (const float*)d_in[1];   // [3136,64,576]
    const float* bias = (const float*)d_in[2];   // [3136,64]
    float* out        = (float*)d_out;           // [32,64,56,56]

    transpose_x<<<dim3(LL / 32, CIN / 32, BATCH), 256>>>(x);

    cudaFuncSetAttribute(lc2d_mma, cudaFuncAttributeMaxDynamicSharedMemorySize, SMEM_TOTAL);
    lc2d_mma<<<LL * 2, NTHREADS, SMEM_TOTAL>>>(w, bias);

    transpose_out<<<dim3(LL / 32, (BATCH * COUT) / 32), 256>>>(out);
}

// round 16
// speedup vs baseline: 1.7840x; 1.7840x over previous
#include <cuda_runtime.h>
#include <cuda.h>
#include <cstdint>

#define BATCH   32
#define CIN     64
#define COUT    64
#define HH      56
#define WW      56
#define LL      3136
#define FEAT    576
#define NCHUNK  18            // 576 / 32 f
#define KTH     6             // chunks per k-third
#define NTHREADS 384          // 12 warps = 4 channel-groups x 3 k-thirds
#define NWARP   12
#define NSTAGE  3
#define DIST    2

// ---- smem ----
#define PROW_BYTES  2320
#define NB          16
#define PATCH_BYTES (NB * PROW_BYTES)       // 37120
#define RING_OFF     37888                  // 1024-aligned
#define WSTAGE_BYTES 2048
#define WRING_BYTES  (NSTAGE * WSTAGE_BYTES)            // 6144
#define MBAR_OFF     (RING_OFF + NWARP * WRING_BYTES)   // 111616
#define SMEM_TOTAL   (MBAR_OFF + NWARP * NSTAGE * 8)    // 111904

__device__ float g_xt[(size_t)BATCH * LL * CIN];
__device__ float g_out_s[(size_t)LL * BATCH * COUT];    // [l][b][c]

// ---------------- helpers ----------------
__device__ __forceinline__ uint32_t swz(uint32_t o) { return o ^ ((o >> 3) & 0x70); }

__device__ __forceinline__ uint32_t cvt_tf32(float v) {
    uint32_t t;
    asm("cvt.rna.tf32.f32 %0, %1;" : "=r"(t) : "f"(v));
    return t;
}
__device__ __forceinline__ uint32_t tf32r(uint32_t bits) {
    uint32_t t;
    asm("cvt.rna.tf32.f32 %0, %1;" : "=r"(t) : "f"(__uint_as_float(bits)));
    return t;
}

__device__ __forceinline__ void sts32(uint32_t a, uint32_t v) {
    asm volatile("st.shared.b32 [%0], %1;" :: "r"(a), "r"(v) : "memory");
}

__device__ __forceinline__ void ldsm_x4(uint32_t addr, uint32_t& r0, uint32_t& r1,
                                        uint32_t& r2, uint32_t& r3) {
    asm volatile("ldmatrix.sync.aligned.m8n8.x4.shared.b16 {%0,%1,%2,%3}, [%4];"
                 : "=r"(r0), "=r"(r1), "=r"(r2), "=r"(r3) : "r"(addr));
}

__device__ __forceinline__ void mma_tf32(float* d, const uint32_t* a, const uint32_t* b) {
    asm volatile("mma.sync.aligned.m16n8k8.row.col.f32.tf32.tf32.f32 "
                 "{%0,%1,%2,%3}, {%4,%5,%6,%7}, {%8,%9}, {%0,%1,%2,%3};"
                 : "+f"(d[0]), "+f"(d[1]), "+f"(d[2]), "+f"(d[3])
                 : "r"(a[0]), "r"(a[1]), "r"(a[2]), "r"(a[3]),
                   "r"(b[0]), "r"(b[1]));
}

__device__ __forceinline__ uint32_t elect1() {
    uint32_t p;
    asm volatile("{\n\t.reg .pred p;\n\telect.sync _|p, 0xFFFFFFFF;\n\tselp.b32 %0, 1, 0, p;\n\t}"
                 : "=r"(p));
    return p;
}

__device__ __forceinline__ void mbar_init(uint32_t mbar, uint32_t cnt) {
    asm volatile("mbarrier.init.shared.b64 [%0], %1;" :: "r"(mbar), "r"(cnt) : "memory");
}
__device__ __forceinline__ void mbar_expect_tx(uint32_t mbar, uint32_t bytes) {
    asm volatile("mbarrier.arrive.expect_tx.shared.b64 _, [%0], %1;"
                 :: "r"(mbar), "r"(bytes) : "memory");
}
__device__ __forceinline__ void mbar_wait(uint32_t mbar, uint32_t parity) {
    asm volatile("{\n\t.reg .pred P;\n\t"
                 "WL_%=:\n\t"
                 "mbarrier.try_wait.parity.acquire.cta.shared::cta.b64 P, [%0], %1, 0x989680;\n\t"
                 "@P bra.uni WD_%=;\n\t"
                 "bra.uni WL_%=;\n\t"
                 "WD_%=:\n\t}"
                 :: "r"(mbar), "r"(parity) : "memory");
}

__device__ __forceinline__ void tma_2d(uint32_t smem_dst, const void* tmap,
                                       int x, int y, uint32_t mbar) {
    asm volatile("cp.async.bulk.tensor.2d.shared::cta.global.tile.mbarrier::complete_tx::bytes "
                 "[%0], [%1, {%2, %3}], [%4];"
                 :: "r"(smem_dst), "l"(tmap), "r"(x), "r"(y), "r"(mbar) : "memory");
}

// ---------------- kernel 1: x NCHW -> NHWC transpose ----------------
__global__ void __launch_bounds__(256) transpose_x(const float* __restrict__ x) {
    __shared__ float tile[32][33];
    const int b  = blockIdx.z;
    const int c0 = blockIdx.y * 32;
    const int s0 = blockIdx.x * 32;
    const int tx = threadIdx.x & 31;
    const int ty = threadIdx.x >> 5;
    #pragma unroll
    for (int i = 0; i < 4; i++)
        tile[ty + 8 * i][tx] = x[((size_t)b * CIN + c0 + ty + 8 * i) * LL + s0 + tx];
    __syncthreads();
    #pragma unroll
    for (int i = 0; i < 4; i++)
        g_xt[((size_t)b * LL + s0 + ty + 8 * i) * CIN + c0 + tx] = tile[tx][ty + 8 * i];
}

// ---------------- kernel 3: scratch [l][b*64+c] -> out [b*64+c][l] ----------------
__global__ void __launch_bounds__(256) transpose_out(float* __restrict__ out) {
    __shared__ float tile[32][33];
    const int l0 = blockIdx.x * 32;
    const int m0 = blockIdx.y * 32;        // m = b*64 + c
    const int tx = threadIdx.x & 31;
    const int ty = threadIdx.x >> 5;
    #pragma unroll
    for (int i = 0; i < 4; i++)
        tile[ty + 8 * i][tx] = g_out_s[(size_t)(l0 + ty + 8 * i) * (BATCH * COUT) + m0 + tx];
    __syncthreads();
    #pragma unroll
    for (int i = 0; i < 4; i++)
        out[(size_t)(m0 + ty + 8 * i) * LL + l0 + tx] = tile[tx][ty + 8 * i];
}

// ---------------- kernel 2: per-(location, batch-half) GEMM, 3-way k-split ----------------
__global__ void __launch_bounds__(NTHREADS, 2)
lc2d_mma(const __grid_constant__ CUtensorMap wmap,
         const float* __restrict__ bias)
{
    extern __shared__ __align__(1024) char smem[];
    const uint32_t sb = (uint32_t)__cvta_generic_to_shared(smem);

    const int tid  = threadIdx.x;
    const int lane = tid & 31;
    const int warp = tid >> 5;        // 0..11
    const int kt   = warp % 3;        // k third: chunks [6*kt, 6*kt+6)
    const int cg   = warp / 3;        // channel group: channels [16*cg, 16*cg+16)
    const int l    = blockIdx.x >> 1;
    const int half = blockIdx.x & 1;  // batches [16*half, 16*half+16)
    const int oh   = l / WW;
    const int ow   = l - oh * WW;

    const uint32_t wring = sb + RING_OFF + (uint32_t)warp * WRING_BYTES;
    const uint32_t wmbar = sb + MBAR_OFF + (uint32_t)warp * (NSTAGE * 8);
    const int      yrow  = l * COUT + cg * 16;
    const int      xbase = kt * (KTH * 32);      // f offset of this warp's k-third

    // ---- init mbarriers ----
    if (tid < NWARP * NSTAGE)
        mbar_init(sb + MBAR_OFF + (uint32_t)tid * 8, 1);
    __syncthreads();

    // ---- prologue: issue chunks 0..1 of this warp's third ----
    if (elect1()) {
        #pragma unroll
        for (int k = 0; k < DIST; k++) {
            mbar_expect_tx(wmbar + (uint32_t)k * 8, WSTAGE_BYTES);
            tma_2d(wring + (uint32_t)k * WSTAGE_BYTES, &wmap, xbase + k * 32, yrow,
                   wmbar + (uint32_t)k * 8);
        }
    }

    // ---- stage patches (16 batches): front-loaded LDGs for MLP ----
    {
        const int pos = tid & 15;                 // cin group: cin = pos*4 + q
        float4   v[6];
        uint32_t adr[6];
        #pragma unroll
        for (int i = 0; i < 6; i++) {
            int s  = (tid >> 4) + i * 24;         // 0..143
            int b  = s / 9;
            int rr = s - b * 9;                   // ki*3 + kj
            int ki = rr / 3, kj = rr - ki * 3;
            int h  = oh + ki - 1;
            int wq = ow + kj - 1;
            bool ok = ((unsigned)h < HH) & ((unsigned)wq < WW);
            v[i] = make_float4(0.f, 0.f, 0.f, 0.f);
            if (ok)
                v[i] = *(const float4*)(g_xt + ((size_t)(half * NB + b) * LL + h * WW + wq) * CIN
                                        + pos * 4);
            adr[i] = sb + (uint32_t)b * PROW_BYTES + (uint32_t)(36 * pos + rr) * 4;
        }
        #pragma unroll
        for (int i = 0; i < 6; i++) {
            sts32(adr[i],       cvt_tf32(v[i].x));
            sts32(adr[i] + 36,  cvt_tf32(v[i].y));
            sts32(adr[i] + 72,  cvt_tf32(v[i].z));
            sts32(adr[i] + 108, cvt_tf32(v[i].w));
        }
    }

    // ---- fragment addressing ----
    const uint32_t a_base = sb + (uint32_t)(lane & 15) * PROW_BYTES
                          + ((lane & 16) ? 16u : 0u);
    // B = weights: [16c][32f] SW128 tile; ldsm_x4 -> 2 n-tiles; swizzle hoisted
    uint32_t b_swz[4];
    {
        const uint32_t b_off = (uint32_t)((lane & 7) + ((lane & 16) ? 8 : 0)) * 128
                             + ((lane & 8) ? 16u : 0u);
        #pragma unroll
        for (int ks = 0; ks < 4; ks++)
            b_swz[ks] = swz(b_off + (uint32_t)ks * 32);
    }

    float acc[2][4];
    #pragma unroll
    for (int nt = 0; nt < 2; nt++)
        #pragma unroll
        for (int q = 0; q < 4; q++) acc[nt][q] = 0.0f;

    __syncthreads();   // patch tile ready

    // ---- main loop: 6 chunks of this warp's k-third; no CTA barriers ----
    #pragma unroll
    for (int k = 0; k < KTH; k++) {
        const int kg = kt * KTH + k;     // global chunk (A column block)

        // preload patch A-frags
        uint32_t a[4][4];
        #pragma unroll
        for (int ks = 0; ks < 4; ks++)
            ldsm_x4(a_base + (uint32_t)(kg * 128 + ks * 32),
                    a[ks][0], a[ks][1], a[ks][2], a[ks][3]);

        // issue chunk k+2 into slot (k+2)%3 (that slot consumed at k-1)
        if (k + DIST < KTH && elect1()) {
            const int kn    = k + DIST;
            const int slot2 = (kn < NSTAGE) ? kn : kn - NSTAGE;
            mbar_expect_tx(wmbar + (uint32_t)slot2 * 8, WSTAGE_BYTES);
            tma_2d(wring + (uint32_t)slot2 * WSTAGE_BYTES, &wmap, xbase + kn * 32, yrow,
                   wmbar + (uint32_t)slot2 * 8);
        }

        // wait for chunk k (slot k%3, parity k>=3)
        const int slot = (k < NSTAGE) ? k : k - NSTAGE;
        mbar_wait(wmbar + (uint32_t)slot * 8, (k < NSTAGE) ? 0u : 1u);

        const uint32_t wt = wring + (uint32_t)slot * WSTAGE_BYTES;
        #pragma unroll
        for (int ks = 0; ks < 4; ks++) {
            uint32_t bf[4];
            ldsm_x4(wt + b_swz[ks], bf[0], bf[1], bf[2], bf[3]);
            #pragma unroll
            for (int q = 0; q < 4; q++) bf[q] = tf32r(bf[q]);
            mma_tf32(acc[0], a[ks], bf);        // channels cg*16 + 0..7
            mma_tf32(acc[1], a[ks], bf + 2);    // channels cg*16 + 8..15
        }
    }

    // ---- cross-warp k-reduction (reuse patch smem) + coalesced epilogue ----
    // D m16n8 layout: d0=(g,2t) d1=(g,2t+1) d2=(g+8,2t) d3=(g+8,2t+1)
    const int g  = lane >> 2;
    const int t2 = (lane & 3) * 2;

    __syncthreads();   // all patch reads done; safe to reuse as reduction area
    float* red = (float*)smem;        // [2 kt-1][4 cg][16 b][16 c] = 8 KB

    if (kt != 0) {
        float* rb = red + ((kt - 1) * 4 + cg) * 256;
        #pragma unroll
        for (int nt = 0; nt < 2; nt++) {
            const int c = nt * 8 + t2;
            rb[(g    ) * 16 + c    ] = acc[nt][0];
            rb[(g    ) * 16 + c + 1] = acc[nt][1];
            rb[(g + 8) * 16 + c    ] = acc[nt][2];
            rb[(g + 8) * 16 + c + 1] = acc[nt][3];
        }
    }
    __syncthreads();

    if (kt == 0) {
        const float* rb1 = red + (0 * 4 + cg) * 256;
        const float* rb2 = red + (1 * 4 + cg) * 256;
        const float* bl = bias + (size_t)l * COUT;
        float* os = g_out_s + (size_t)l * (BATCH * COUT) + (half * NB) * COUT;
        #pragma unroll
        for (int nt = 0; nt < 2; nt++) {
            const int cl = nt * 8 + t2;
            const int c  = cg * 16 + cl;
            const float bv0 = bl[c];
            const float bv1 = bl[c + 1];
            float2 v0, v1;
            v0.x = acc[nt][0] + rb1[(g    ) * 16 + cl    ] + rb2[(g    ) * 16 + cl    ] + bv0;
            v0.y = acc[nt][1] + rb1[(g    ) * 16 + cl + 1] + rb2[(g    ) * 16 + cl + 1] + bv1;
            v1.x = acc[nt][2] + rb1[(g + 8) * 16 + cl    ] + rb2[(g + 8) * 16 + cl    ] + bv0;
            v1.y = acc[nt][3] + rb1[(g + 8) * 16 + cl + 1] + rb2[(g + 8) * 16 + cl + 1] + bv1;
            *(float2*)(os + (size_t)(g    ) * COUT + c) = v0;
            *(float2*)(os + (size_t)(g + 8) * COUT + c) = v1;
        }
    }
}

// ---------------- host ----------------
typedef CUresult (*EncodeTiledFn)(
    CUtensorMap*, CUtensorMapDataType, cuuint32_t, void*,
    const cuuint64_t*, const cuuint64_t*, const cuuint32_t*, const cuuint32_t*,
    CUtensorMapInterleave, CUtensorMapSwizzle, CUtensorMapL2promotion,
    CUtensorMapFloatOOBfill);

extern "C" void kernel_launch(void* const* d_in, const int* in_sizes, int n_in,
                              void* d_out, int out_size)
{
    const float* x    = (const float*)d_in[0];   // [32,64,56,56]
    const float* w    = (const float*)d_in[1];   // [3136,64,576]
    const float* bias = (const float*)d_in[2];   // [3136,64]
    float* out        = (float*)d_out;           // [32,64,56,56]

    // weight tensor map: 2D [576 f][200704 rows = c + 64*l], box [32, 16], SW128
    void* fp = nullptr;
    cudaDriverEntryPointQueryResult qr;
    cudaGetDriverEntryPointByVersion("cuTensorMapEncodeTiled", &fp, 12000,
                                     cudaEnableDefault, &qr);
    EncodeTiledFn encode = (EncodeTiledFn)fp;

    CUtensorMap wmap;
    cuuint64_t dims[2]    = {(cuuint64_t)FEAT, (cuuint64_t)LL * COUT};
    cuuint64_t strides[1] = {(cuuint64_t)FEAT * sizeof(float)};
    cuuint32_t box[2]     = {32, 16};
    cuuint32_t estr[2]    = {1, 1};
    encode(&wmap, CU_TENSOR_MAP_DATA_TYPE_FLOAT32, 2, (void*)w,
           dims, strides, box, estr,
           CU_TENSOR_MAP_INTERLEAVE_NONE, CU_TENSOR_MAP_SWIZZLE_128B,
           CU_TENSOR_MAP_L2_PROMOTION_L2_128B, CU_TENSOR_MAP_FLOAT_OOB_FILL_NONE);

    transpose_x<<<dim3(LL / 32, CIN / 32, BATCH), 256>>>(x);

    cudaFuncSetAttribute(lc2d_mma, cudaFuncAttributeMaxDynamicSharedMemorySize, SMEM_TOTAL);
    lc2d_mma<<<LL * 2, NTHREADS, SMEM_TOTAL>>>(wmap, bias);

    transpose_out<<<dim3(LL / 32, (BATCH * COUT) / 32), 256>>>(out);
}

// round 17
// speedup vs baseline: 1.8625x; 1.0440x over previous
#include <cuda_runtime.h>
#include <cuda.h>
#include <cstdint>

#define BATCH   32
#define CIN     64
#define COUT    64
#define HH      56
#define WW      56
#define LL      3136
#define FEAT    576
#define NCHUNK  18            // 576 / 32 f
#define KHALF   9             // chunks per k-half
#define NTHREADS 256          // 8 warps = 4 channel-groups x 2 k-halves
#define NWARP   8
#define NSTAGE  4
#define DIST    3

// ---- smem ----
#define PROW_BYTES  2320
#define NB          16
#define PATCH_BYTES (NB * PROW_BYTES)       // 37120
#define RING_OFF     37888                  // 1024-aligned
#define WSTAGE_BYTES 2048
#define WRING_BYTES  (NSTAGE * WSTAGE_BYTES)            // 8192
#define MBAR_OFF     (RING_OFF + NWARP * WRING_BYTES)   // 103424
#define SMEM_TOTAL   (MBAR_OFF + NWARP * NSTAGE * 8)    // 103680

__device__ float g_xt[(size_t)BATCH * LL * CIN];
__device__ float g_out_s[(size_t)LL * BATCH * COUT];    // [l][b*64+c]

// ---------------- helpers ----------------
__device__ __forceinline__ uint32_t swz(uint32_t o) { return o ^ ((o >> 3) & 0x70); }

__device__ __forceinline__ uint32_t cvt_tf32(float v) {
    uint32_t t;
    asm("cvt.rna.tf32.f32 %0, %1;" : "=r"(t) : "f"(v));
    return t;
}
__device__ __forceinline__ uint32_t tf32r(uint32_t bits) {
    uint32_t t;
    asm("cvt.rna.tf32.f32 %0, %1;" : "=r"(t) : "f"(__uint_as_float(bits)));
    return t;
}

__device__ __forceinline__ void sts32(uint32_t a, uint32_t v) {
    asm volatile("st.shared.b32 [%0], %1;" :: "r"(a), "r"(v) : "memory");
}

__device__ __forceinline__ void ldsm_x4(uint32_t addr, uint32_t& r0, uint32_t& r1,
                                        uint32_t& r2, uint32_t& r3) {
    asm volatile("ldmatrix.sync.aligned.m8n8.x4.shared.b16 {%0,%1,%2,%3}, [%4];"
                 : "=r"(r0), "=r"(r1), "=r"(r2), "=r"(r3) : "r"(addr));
}

__device__ __forceinline__ void mma_tf32(float* d, const uint32_t* a, const uint32_t* b) {
    asm volatile("mma.sync.aligned.m16n8k8.row.col.f32.tf32.tf32.f32 "
                 "{%0,%1,%2,%3}, {%4,%5,%6,%7}, {%8,%9}, {%0,%1,%2,%3};"
                 : "+f"(d[0]), "+f"(d[1]), "+f"(d[2]), "+f"(d[3])
                 : "r"(a[0]), "r"(a[1]), "r"(a[2]), "r"(a[3]),
                   "r"(b[0]), "r"(b[1]));
}

__device__ __forceinline__ uint32_t elect1() {
    uint32_t p;
    asm volatile("{\n\t.reg .pred p;\n\telect.sync _|p, 0xFFFFFFFF;\n\tselp.b32 %0, 1, 0, p;\n\t}"
                 : "=r"(p));
    return p;
}

__device__ __forceinline__ void mbar_init(uint32_t mbar, uint32_t cnt) {
    asm volatile("mbarrier.init.shared.b64 [%0], %1;" :: "r"(mbar), "r"(cnt) : "memory");
}
__device__ __forceinline__ void mbar_expect_tx(uint32_t mbar, uint32_t bytes) {
    asm volatile("mbarrier.arrive.expect_tx.shared.b64 _, [%0], %1;"
                 :: "r"(mbar), "r"(bytes) : "memory");
}
__device__ __forceinline__ void mbar_wait(uint32_t mbar, uint32_t parity) {
    asm volatile("{\n\t.reg .pred P;\n\t"
                 "WL_%=:\n\t"
                 "mbarrier.try_wait.parity.acquire.cta.shared::cta.b64 P, [%0], %1, 0x989680;\n\t"
                 "@P bra.uni WD_%=;\n\t"
                 "bra.uni WL_%=;\n\t"
                 "WD_%=:\n\t}"
                 :: "r"(mbar), "r"(parity) : "memory");
}

__device__ __forceinline__ void tma_2d(uint32_t smem_dst, const void* tmap,
                                       int x, int y, uint32_t mbar) {
    asm volatile("cp.async.bulk.tensor.2d.shared::cta.global.tile.mbarrier::complete_tx::bytes "
                 "[%0], [%1, {%2, %3}], [%4];"
                 :: "r"(smem_dst), "l"(tmap), "r"(x), "r"(y), "r"(mbar) : "memory");
}

// ---------------- kernel 1: x [b][c][l] -> g_xt [b][l][c], float4 both ways ----------------
__global__ void __launch_bounds__(256) transpose_x(const float* __restrict__ x) {
    __shared__ float tile[64][65];       // [c][l], pad 65 -> <=2-way conflicts
    const int b  = blockIdx.z;
    const int l0 = blockIdx.x * 64;
    const int r  = threadIdx.x >> 4;     // 0..15
    const int q  = threadIdx.x & 15;     // 0..15

    #pragma unroll
    for (int i = 0; i < 4; i++) {
        const int c = r + 16 * i;
        float4 v = *(const float4*)(x + ((size_t)(b * CIN + c)) * LL + l0 + 4 * q);
        tile[c][4 * q + 0] = v.x;
        tile[c][4 * q + 1] = v.y;
        tile[c][4 * q + 2] = v.z;
        tile[c][4 * q + 3] = v.w;
    }
    __syncthreads();
    #pragma unroll
    for (int i = 0; i < 4; i++) {
        const int l = r + 16 * i;
        float4 u;
        u.x = tile[4 * q + 0][l];
        u.y = tile[4 * q + 1][l];
        u.z = tile[4 * q + 2][l];
        u.w = tile[4 * q + 3][l];
        *(float4*)(g_xt + ((size_t)b * LL + l0 + l) * CIN + 4 * q) = u;
    }
}

// ---------------- kernel 3: g_out_s [l][m] -> out [m][l], float4 both ways ----------------
__global__ void __launch_bounds__(256) transpose_out(float* __restrict__ out) {
    __shared__ float tile[64][65];       // [l][m]
    const int l0 = blockIdx.x * 64;
    const int m0 = blockIdx.y * 64;      // m = b*64 + c
    const int r  = threadIdx.x >> 4;
    const int q  = threadIdx.x & 15;
    const int M  = BATCH * COUT;         // 2048

    #pragma unroll
    for (int i = 0; i < 4; i++) {
        const int l = r + 16 * i;
        float4 v = *(const float4*)(g_out_s + (size_t)(l0 + l) * M + m0 + 4 * q);
        tile[l][4 * q + 0] = v.x;
        tile[l][4 * q + 1] = v.y;
        tile[l][4 * q + 2] = v.z;
        tile[l][4 * q + 3] = v.w;
    }
    __syncthreads();
    #pragma unroll
    for (int i = 0; i < 4; i++) {
        const int m = r + 16 * i;
        float4 u;
        u.x = tile[4 * q + 0][m];
        u.y = tile[4 * q + 1][m];
        u.z = tile[4 * q + 2][m];
        u.w = tile[4 * q + 3][m];
        *(float4*)(out + (size_t)(m0 + m) * LL + l0 + 4 * q) = u;
    }
}

// ---------------- kernel 2: per-(location, batch-half) GEMM, k-split warps ----------------
__global__ void __launch_bounds__(NTHREADS, 2)
lc2d_mma(const __grid_constant__ CUtensorMap wmap,
         const float* __restrict__ bias)
{
    extern __shared__ __align__(1024) char smem[];
    const uint32_t sb = (uint32_t)__cvta_generic_to_shared(smem);

    const int tid  = threadIdx.x;
    const int lane = tid & 31;
    const int warp = tid >> 5;
    const int kh   = warp & 1;        // k half: chunks [9*kh, 9*kh+9)
    const int cg   = warp >> 1;       // channel group: channels [16*cg, 16*cg+16)
    const int l    = blockIdx.x >> 1;
    const int half = blockIdx.x & 1;  // batches [16*half, 16*half+16)
    const int oh   = l / WW;
    const int ow   = l - oh * WW;

    const uint32_t wring = sb + RING_OFF + (uint32_t)warp * WRING_BYTES;
    const uint32_t wmbar = sb + MBAR_OFF + (uint32_t)warp * (NSTAGE * 8);
    const int      yrow  = l * COUT + cg * 16;
    const int      xbase = kh * (KHALF * 32);    // f offset of this warp's k-half

    // ---- init mbarriers ----
    if (tid < NWARP * NSTAGE)
        mbar_init(sb + MBAR_OFF + (uint32_t)tid * 8, 1);
    __syncthreads();

    // ---- prologue: issue chunks 0..2 of this warp's half ----
    if (elect1()) {
        #pragma unroll
        for (int k = 0; k < DIST; k++) {
            mbar_expect_tx(wmbar + (uint32_t)k * 8, WSTAGE_BYTES);
            tma_2d(wring + (uint32_t)k * WSTAGE_BYTES, &wmap, xbase + k * 32, yrow,
                   wmbar + (uint32_t)k * 8);
        }
    }

    // ---- stage patches (16 batches): front-loaded LDGs for MLP ----
    {
        const int pos = tid & 15;                 // cin group: cin = pos*4 + q
        float4   v[9];
        uint32_t adr[9];
        #pragma unroll
        for (int i = 0; i < 9; i++) {
            int s  = (tid >> 4) + i * 16;         // 0..143
            int b  = s / 9;
            int rr = s - b * 9;                   // ki*3 + kj
            int ki = rr / 3, kj = rr - ki * 3;
            int h  = oh + ki - 1;
            int wq = ow + kj - 1;
            bool ok = ((unsigned)h < HH) & ((unsigned)wq < WW);
            v[i] = make_float4(0.f, 0.f, 0.f, 0.f);
            if (ok)
                v[i] = *(const float4*)(g_xt + ((size_t)(half * NB + b) * LL + h * WW + wq) * CIN
                                        + pos * 4);
            adr[i] = sb + (uint32_t)b * PROW_BYTES + (uint32_t)(36 * pos + rr) * 4;
        }
        #pragma unroll
        for (int i = 0; i < 9; i++) {
            sts32(adr[i],       cvt_tf32(v[i].x));
            sts32(adr[i] + 36,  cvt_tf32(v[i].y));
            sts32(adr[i] + 72,  cvt_tf32(v[i].z));
            sts32(adr[i] + 108, cvt_tf32(v[i].w));
        }
    }

    // ---- fragment addressing ----
    const uint32_t a_base = sb + (uint32_t)(lane & 15) * PROW_BYTES
                          + ((lane & 16) ? 16u : 0u);
    // B = weights: [16c][32f] SW128 tile; ldsm_x4 -> 2 n-tiles; swizzle hoisted
    uint32_t b_swz[4];
    {
        const uint32_t b_off = (uint32_t)((lane & 7) + ((lane & 16) ? 8 : 0)) * 128
                             + ((lane & 8) ? 16u : 0u);
        #pragma unroll
        for (int ks = 0; ks < 4; ks++)
            b_swz[ks] = swz(b_off + (uint32_t)ks * 32);
    }

    float acc[2][4];
    #pragma unroll
    for (int nt = 0; nt < 2; nt++)
        #pragma unroll
        for (int q = 0; q < 4; q++) acc[nt][q] = 0.0f;

    __syncthreads();   // patch tile ready

    // ---- main loop: 9 chunks of this warp's k-half; no CTA barriers ----
    #pragma unroll
    for (int k = 0; k < KHALF; k++) {
        const int kg = kh * KHALF + k;     // global chunk (A column block)

        // preload patch A-frags
        uint32_t a[4][4];
        #pragma unroll
        for (int ks = 0; ks < 4; ks++)
            ldsm_x4(a_base + (uint32_t)(kg * 128 + ks * 32),
                    a[ks][0], a[ks][1], a[ks][2], a[ks][3]);

        // issue chunk k+3 into slot (k+3)&3 (consumed at k-1)
        if (k + DIST < KHALF && elect1()) {
            const int kn    = k + DIST;
            const int slot2 = kn & (NSTAGE - 1);
            mbar_expect_tx(wmbar + (uint32_t)slot2 * 8, WSTAGE_BYTES);
            tma_2d(wring + (uint32_t)slot2 * WSTAGE_BYTES, &wmap, xbase + kn * 32, yrow,
                   wmbar + (uint32_t)slot2 * 8);
        }

        // wait for chunk k (slot k&3, parity (k>>2)&1)
        const int slot = k & (NSTAGE - 1);
        mbar_wait(wmbar + (uint32_t)slot * 8, (uint32_t)((k >> 2) & 1));

        const uint32_t wt = wring + (uint32_t)slot * WSTAGE_BYTES;
        #pragma unroll
        for (int ks = 0; ks < 4; ks++) {
            uint32_t bf[4];
            ldsm_x4(wt + b_swz[ks], bf[0], bf[1], bf[2], bf[3]);
            #pragma unroll
            for (int q = 0; q < 4; q++) bf[q] = tf32r(bf[q]);
            mma_tf32(acc[0], a[ks], bf);        // channels cg*16 + 0..7
            mma_tf32(acc[1], a[ks], bf + 2);    // channels cg*16 + 8..15
        }
    }

    // ---- cross-warp k-reduction (reuse patch smem) + coalesced epilogue ----
    // D m16n8 layout: d0=(g,2t) d1=(g,2t+1) d2=(g+8,2t) d3=(g+8,2t+1)
    const int g  = lane >> 2;
    const int t2 = (lane & 3) * 2;

    __syncthreads();   // all patch reads done; safe to reuse as reduction area
    float* red = (float*)smem;        // [4 cg][16 b][16 c] = 4 KB

    if (kh == 1) {
        float* rb = red + cg * 256;
        #pragma unroll
        for (int nt = 0; nt < 2; nt++) {
            const int c = nt * 8 + t2;
            rb[(g    ) * 16 + c    ] = acc[nt][0];
            rb[(g    ) * 16 + c + 1] = acc[nt][1];
            rb[(g + 8) * 16 + c    ] = acc[nt][2];
            rb[(g + 8) * 16 + c + 1] = acc[nt][3];
        }
    }
    __syncthreads();

    if (kh == 0) {
        const float* rb = red + cg * 256;
        const float* bl = bias + (size_t)l * COUT;
        float* os = g_out_s + (size_t)l * (BATCH * COUT) + (half * NB) * COUT;
        #pragma unroll
        for (int nt = 0; nt < 2; nt++) {
            const int cl = nt * 8 + t2;
            const int c  = cg * 16 + cl;
            const float bv0 = bl[c];
            const float bv1 = bl[c + 1];
            float2 v0, v1;
            v0.x = acc[nt][0] + rb[(g    ) * 16 + cl    ] + bv0;
            v0.y = acc[nt][1] + rb[(g    ) * 16 + cl + 1] + bv1;
            v1.x = acc[nt][2] + rb[(g + 8) * 16 + cl    ] + bv0;
            v1.y = acc[nt][3] + rb[(g + 8) * 16 + cl + 1] + bv1;
            *(float2*)(os + (size_t)(g    ) * COUT + c) = v0;
            *(float2*)(os + (size_t)(g + 8) * COUT + c) = v1;
        }
    }
}

// ---------------- host ----------------
typedef CUresult (*EncodeTiledFn)(
    CUtensorMap*, CUtensorMapDataType, cuuint32_t, void*,
    const cuuint64_t*, const cuuint64_t*, const cuuint32_t*, const cuuint32_t*,
    CUtensorMapInterleave, CUtensorMapSwizzle, CUtensorMapL2promotion,
    CUtensorMapFloatOOBfill);

extern "C" void kernel_launch(void* const* d_in, const int* in_sizes, int n_in,
                              void* d_out, int out_size)
{
    const float* x    = (const float*)d_in[0];   // [32,64,56,56]
    const float* w    = (const float*)d_in[1];   // [3136,64,576]
    const float* bias = (const float*)d_in[2];   // [3136,64]
    float* out        = (float*)d_out;           // [32,64,56,56]

    // weight tensor map: 2D [576 f][200704 rows = c + 64*l], box [32, 16], SW128
    void* fp = nullptr;
    cudaDriverEntryPointQueryResult qr;
    cudaGetDriverEntryPointByVersion("cuTensorMapEncodeTiled", &fp, 12000,
                                     cudaEnableDefault, &qr);
    EncodeTiledFn encode = (EncodeTiledFn)fp;

    CUtensorMap wmap;
    cuuint64_t dims[2]    = {(cuuint64_t)FEAT, (cuuint64_t)LL * COUT};
    cuuint64_t strides[1] = {(cuuint64_t)FEAT * sizeof(float)};
    cuuint32_t box[2]     = {32, 16};
    cuuint32_t estr[2]    = {1, 1};
    encode(&wmap, CU_TENSOR_MAP_DATA_TYPE_FLOAT32, 2, (void*)w,
           dims, strides, box, estr,
           CU_TENSOR_MAP_INTERLEAVE_NONE, CU_TENSOR_MAP_SWIZZLE_128B,
           CU_TENSOR_MAP_L2_PROMOTION_L2_128B, CU_TENSOR_MAP_FLOAT_OOB_FILL_NONE);

    transpose_x<<<dim3(LL / 64, 1, BATCH), 256>>>(x);

    cudaFuncSetAttribute(lc2d_mma, cudaFuncAttributeMaxDynamicSharedMemorySize, SMEM_TOTAL);
    lc2d_mma<<<LL * 2, NTHREADS, SMEM_TOTAL>>>(wmap, bias);

    transpose_out<<<dim3(LL / 64, (BATCH * COUT) / 64), 256>>>(out);
}